// round 1
// baseline (speedup 1.0000x reference)
#include <cuda_runtime.h>
#include <cstdint>

// Overlap-add (TorchOLA): inputs [B, NF, FS] fp32, frame_shift S.
// B=32, NF=4000, FS=320, S=160, sig_length = (NF-1)*S + FS = 640160.
// Since FS == 2*S, each output sample t gets contributions from at most two
// frames: f1 = t/S at offset (t - f1*S), and f1-1 at offset (t - f1*S + S).
// count == 2 except the first S and last S samples (count == 1).
// Gather formulation: 2 coalesced reads + 1 write, no atomics.

namespace {
constexpr int NF = 4000;
constexpr int FS = 320;
constexpr int SHIFT = 160;
constexpr int SIG_LEN = (NF - 1) * SHIFT + FS;     // 640160
constexpr int VECS_PER_BATCH = SIG_LEN / 4;        // 160040
constexpr int FRAME_VECS = FS / 4;                 // 80
constexpr int THREADS = 256;
}

__global__ void __launch_bounds__(THREADS)
ola_kernel(const float4* __restrict__ in, float4* __restrict__ out) {
    const int tv = blockIdx.x * THREADS + threadIdx.x;  // vec index within batch
    if (tv >= VECS_PER_BATCH) return;
    const int b = blockIdx.y;

    const int t = tv * 4;
    // f1 = t / SHIFT (0..NF); offset within frame f1
    const unsigned f1 = (unsigned)t / (unsigned)SHIFT;
    const int off = t - (int)f1 * SHIFT;               // multiple of 4, in [0,160)

    const float4* __restrict__ base = in + (size_t)b * (size_t)(NF * FRAME_VECS);

    float4 acc = make_float4(0.f, 0.f, 0.f, 0.f);
    float scale = 0.5f;

    if (f1 < NF) {
        // frame f1 at offset [off, off+3]
        acc = base[(size_t)f1 * FRAME_VECS + (off >> 2)];
    } else {
        scale = 1.0f;  // t beyond last frame's start region: only frame NF-1
    }
    if (f1 > 0) {
        // frame f1-1 at offset [off+SHIFT, off+SHIFT+3]
        const float4 c = base[(size_t)(f1 - 1) * FRAME_VECS + ((off + SHIFT) >> 2)];
        acc.x += c.x; acc.y += c.y; acc.z += c.z; acc.w += c.w;
    } else {
        scale = 1.0f;  // first SHIFT samples: only frame 0
    }

    acc.x *= scale; acc.y *= scale; acc.z *= scale; acc.w *= scale;
    out[(size_t)b * VECS_PER_BATCH + tv] = acc;
}

extern "C" void kernel_launch(void* const* d_in, const int* in_sizes, int n_in,
                              void* d_out, int out_size) {
    const float4* in = (const float4*)d_in[0];
    float4* out = (float4*)d_out;

    // derive batch from input element count (NF*FS elems per batch)
    const int B = in_sizes[0] / (NF * FS);

    dim3 grid((VECS_PER_BATCH + THREADS - 1) / THREADS, B, 1);
    ola_kernel<<<grid, THREADS>>>(in, out);
}